// round 11
// baseline (speedup 1.0000x reference)
#include <cuda_runtime.h>

// Problem constants (shapes fixed by the dataset)
#define NU   10000
#define NI   30000
#define NN   40000      // NU + NI
#define HID  256
#define NE   500000
#define AH   32
#define THR  0.8f

// ---------------- device scratch (no allocation allowed) ----------------
__device__ float g_A[NU * AH];             // U @ W1_top + b1
__device__ float g_B[NI * AH];             // I @ W1_bot
__device__ float g_w[NE];                  // raw sigmoid edge weights
__device__ float g_deg[NN];                // degree (self-loop = 1)
__device__ float g_Y[(size_t)NN * HID];    // dinv[row] * (x @ gcn_W)
__device__ int   g_kept[NE];               // compacted kept-edge ids
__device__ int   g_nkept;
__device__ int   g_any;
__device__ unsigned long long g_amax;      // packed (w_bits << 32) | ~idx

// ---------------- K1: A = U@W1u + b1 ; B = I@W1i  (+ fused state reset) -----
// 8 rows per block, warp per row. W1 half transposed into smem.
// Prologue also resets per-replay mutable state (g_deg, flags); all consumers
// of that state run in strictly later kernels, so this is order-equivalent
// to a standalone init kernel.
__global__ __launch_bounds__(256) void k_ab(const float* __restrict__ U,
                                            const float* __restrict__ Iemb,
                                            const float* __restrict__ W1,
                                            const float* __restrict__ b1) {
    __shared__ __align__(16) float Wt[AH * 260];  // [j][k], stride 260 (16B-aligned rows)
    int tid  = threadIdx.x;
    int gt   = blockIdx.x * 256 + tid;
    if (gt < NN) g_deg[gt] = 1.0f;
    if (gt == 0) { g_any = 0; g_nkept = 0; g_amax = 0ull; }

    int row0 = blockIdx.x * 8;
    int half = (row0 >= NU) ? 1 : 0;    // 10000 % 8 == 0, no block crosses boundary
    const float* Wbase = W1 + half * HID * AH;
    for (int idx = tid; idx < HID * AH; idx += 256)
        Wt[(idx & 31) * 260 + (idx >> 5)] = Wbase[idx];
    __syncthreads();

    int r = tid >> 5;
    int j = tid & 31;
    int row = row0 + r;
    const float* xrow = half ? (Iemb + (size_t)(row - NU) * HID)
                             : (U + (size_t)row * HID);
    float acc = half ? 0.f : b1[j];
    const float* wrow = &Wt[j * 260];
#pragma unroll 8
    for (int k = 0; k < HID; k += 4) {
        float4 x4 = *(const float4*)(xrow + k);   // broadcast across warp
        float4 w4 = *(const float4*)(wrow + k);
        acc += x4.x * w4.x + x4.y * w4.y + x4.z * w4.z + x4.w * w4.w;
    }
    if (half) g_B[(row - NU) * AH + j] = acc;
    else      g_A[row * AH + j] = acc;
}

// ---------------- K2: per-edge MLP + sigmoid (warp per edge) ----------------
__global__ __launch_bounds__(256) void k_edge(const int* __restrict__ ei,
                                              const float* __restrict__ W2,
                                              const float* __restrict__ b2) {
    int gt   = blockIdx.x * blockDim.x + threadIdx.x;
    int e    = gt >> 5;
    int lane = gt & 31;
    if (e >= NE) return;
    int s = __ldg(&ei[e]);
    int d = __ldg(&ei[NE + e]);
    float h = g_A[s * AH + lane] + g_B[d * AH + lane];
    h = (h > 0.f) ? h : 0.2f * h;                  // leaky_relu(0.2)
    float p = h * W2[lane];
#pragma unroll
    for (int o = 16; o; o >>= 1) p += __shfl_xor_sync(0xffffffffu, p, o);
    if (lane == 0) {
        float wgt = 1.f / (1.f + expf(-(p + b2[0])));
        g_w[e] = wgt;
        if (wgt > THR) g_any = 1;   // benign race: all writers store 1
    }
}

// ---------------- K3: argmax fallback (only does work if no edge passed) ----
__global__ void k_argmax() {
    if (g_any) return;   // common case: immediate exit
    __shared__ unsigned long long smax;
    if (threadIdx.x == 0) smax = 0ull;
    __syncthreads();
    unsigned long long best = 0ull;
    for (int e = blockIdx.x * blockDim.x + threadIdx.x; e < NE;
         e += gridDim.x * blockDim.x) {
        // w in (0,1) -> positive float bits are order-preserving as uint.
        // ~e as tiebreak: larger packed == smaller index (jnp.argmax = first max).
        unsigned long long pk =
            ((unsigned long long)__float_as_uint(g_w[e]) << 32) |
            (unsigned int)(~(unsigned int)e);
        if (pk > best) best = pk;
    }
    atomicMax(&smax, best);
    __syncthreads();
    if (threadIdx.x == 0) atomicMax(&g_amax, smax);
}

// ------- K4: mask + denoised weights out + degree atomics + compaction -------
__global__ __launch_bounds__(256) void k_mask(const int* __restrict__ ei,
                                              float* __restrict__ out_w) {
    __shared__ int s_base;
    __shared__ int warp_off[8];
    int e    = blockIdx.x * blockDim.x + threadIdx.x;
    int lane = threadIdx.x & 31;
    int warp = threadIdx.x >> 5;
    bool keep = false;
    if (e < NE) {
        float w = g_w[e];
        keep = (w > THR);
        if (!g_any) {
            int am = (int)(~(unsigned int)(g_amax & 0xffffffffull));
            keep = (e == am);
        }
        out_w[e] = keep ? w : 0.f;
        if (keep) atomicAdd(&g_deg[ei[NE + e]], 1.0f);
    }
    unsigned bal = __ballot_sync(0xffffffffu, keep);
    if (lane == 0) warp_off[warp] = __popc(bal);
    __syncthreads();
    if (threadIdx.x == 0) {
        int tot = 0;
#pragma unroll
        for (int i = 0; i < 8; i++) { int c = warp_off[i]; warp_off[i] = tot; tot += c; }
        s_base = atomicAdd(&g_nkept, tot);
    }
    __syncthreads();
    if (keep) {
        int idx = s_base + warp_off[warp] + __popc(bal & ((1u << lane) - 1));
        g_kept[idx] = e;
    }
}

// ---------------- K5: y = dinv[row] * (x @ gcn_W); acc(=d_out) = y ----------
// 128x128 tile, BK=16, 256 threads, 8x8 register tile per thread.
// dinv computed inline from g_deg (rsqrtf, deterministic).
__global__ __launch_bounds__(256, 2) void k_gemm(const float* __restrict__ U,
                                                 const float* __restrict__ Iemb,
                                                 const float* __restrict__ W,
                                                 float* __restrict__ outAcc) {
    __shared__ __align__(16) float As[128 * 17];   // [r][k], padded
    __shared__ __align__(16) float Bs[16 * 128];   // [k][c]
    int tid = threadIdx.x;
    int tx = tid & 15, ty = tid >> 4;
    int bn = blockIdx.x * 128;
    int bm = blockIdx.y * 128;

    float acc[8][8];
#pragma unroll
    for (int i = 0; i < 8; i++)
#pragma unroll
        for (int j = 0; j < 8; j++) acc[i][j] = 0.f;

    for (int k0 = 0; k0 < 256; k0 += 16) {
#pragma unroll
        for (int l = 0; l < 2; l++) {           // A tile: 128x16
            int f = tid + l * 256;              // float4 index
            int r = f >> 2, c4 = f & 3;
            int row = bm + r;
            float4 v = make_float4(0.f, 0.f, 0.f, 0.f);
            if (row < NN) {
                const float* xr = (row < NU) ? (U + (size_t)row * HID)
                                             : (Iemb + (size_t)(row - NU) * HID);
                v = *(const float4*)(xr + k0 + c4 * 4);
            }
            As[r * 17 + c4 * 4 + 0] = v.x;
            As[r * 17 + c4 * 4 + 1] = v.y;
            As[r * 17 + c4 * 4 + 2] = v.z;
            As[r * 17 + c4 * 4 + 3] = v.w;
        }
#pragma unroll
        for (int l = 0; l < 2; l++) {           // B tile: 16x128
            int f = tid + l * 256;
            int k = f >> 5, c4 = f & 31;
            float4 v = *(const float4*)(W + (size_t)(k0 + k) * 256 + bn + c4 * 4);
            *(float4*)&Bs[k * 128 + c4 * 4] = v;
        }
        __syncthreads();
#pragma unroll
        for (int kk = 0; kk < 16; kk++) {
            float a[8], b[8];
#pragma unroll
            for (int i = 0; i < 8; i++) a[i] = As[(ty * 8 + i) * 17 + kk];
            float4 b0 = *(float4*)&Bs[kk * 128 + tx * 8];
            float4 b1 = *(float4*)&Bs[kk * 128 + tx * 8 + 4];
            b[0] = b0.x; b[1] = b0.y; b[2] = b0.z; b[3] = b0.w;
            b[4] = b1.x; b[5] = b1.y; b[6] = b1.z; b[7] = b1.w;
#pragma unroll
            for (int i = 0; i < 8; i++)
#pragma unroll
                for (int j = 0; j < 8; j++) acc[i][j] += a[i] * b[j];
        }
        __syncthreads();
    }

#pragma unroll
    for (int i = 0; i < 8; i++) {
        int row = bm + ty * 8 + i;
        if (row < NN) {
            float dv = rsqrtf(g_deg[row]);
#pragma unroll
            for (int j = 0; j < 2; j++) {
                float4 v;
                v.x = acc[i][4 * j + 0] * dv;
                v.y = acc[i][4 * j + 1] * dv;
                v.z = acc[i][4 * j + 2] * dv;
                v.w = acc[i][4 * j + 3] * dv;
                size_t off = (size_t)row * HID + bn + tx * 8 + j * 4;
                *(float4*)(g_Y + off)   = v;   // read source for messages
                *(float4*)(outAcc + off) = v;  // accumulator (self term)
            }
        }
    }
}

// ---------------- K6: scatter kept-edge messages: acc[dst] += y[src] --------
__global__ __launch_bounds__(256) void k_scatter(const int* __restrict__ ei,
                                                 float* __restrict__ outAcc) {
    int nk    = g_nkept;
    int lane  = threadIdx.x & 31;
    int wid   = (blockIdx.x * blockDim.x + threadIdx.x) >> 5;
    int nwarp = (gridDim.x * blockDim.x) >> 5;
    for (int i = wid; i < nk; i += nwarp) {
        int e = g_kept[i];
        int s = ei[e];
        int d = ei[NE + e];
        const float4* ys = (const float4*)(g_Y + (size_t)s * HID);
        float4* od = (float4*)(outAcc + (size_t)d * HID);
#pragma unroll
        for (int jj = 0; jj < 2; jj++) {
            float4 v = ys[lane + 32 * jj];
            asm volatile("red.global.add.v4.f32 [%0], {%1, %2, %3, %4};"
                         :: "l"(od + lane + 32 * jj),
                            "f"(v.x), "f"(v.y), "f"(v.z), "f"(v.w)
                         : "memory");
        }
    }
}

// ---------------- K7: out = dinv[row]*acc + gcn_b ----------------
__global__ void k_final(float* __restrict__ out, const float* __restrict__ gb) {
    int i = blockIdx.x * blockDim.x + threadIdx.x;
    if (i >= NN * HID / 4) return;
    float4 v = ((float4*)out)[i];
    int row = i >> 6;    // 64 float4 per row
    int c4  = i & 63;
    float dv = rsqrtf(g_deg[row]);
    float4 b = ((const float4*)gb)[c4];
    v.x = v.x * dv + b.x;
    v.y = v.y * dv + b.y;
    v.z = v.z * dv + b.z;
    v.w = v.w * dv + b.w;
    ((float4*)out)[i] = v;
}

// ---------------- launch ----------------
extern "C" void kernel_launch(void* const* d_in, const int* in_sizes, int n_in,
                              void* d_out, int out_size) {
    const float* U  = (const float*)d_in[0];   // [10000,256]
    const float* Ie = (const float*)d_in[1];   // [30000,256]
    const int*   EI = (const int*)  d_in[2];   // [2,500000]
    const float* W1 = (const float*)d_in[3];   // [512,32]
    const float* B1 = (const float*)d_in[4];   // [32]
    const float* W2 = (const float*)d_in[5];   // [32,1]
    const float* B2 = (const float*)d_in[6];   // [1]
    const float* GW = (const float*)d_in[7];   // [256,256]
    const float* GB = (const float*)d_in[8];   // [256]
    float* out  = (float*)d_out;               // [40000,256] then [500000]
    float* outW = out + (size_t)NN * HID;

    k_ab     <<<NN / 8, 256>>>(U, Ie, W1, B1);   // includes state reset
    k_edge   <<<(NE * 32) / 256, 256>>>(EI, W2, B2);
    k_argmax <<<256, 256>>>();
    k_mask   <<<(NE + 255) / 256, 256>>>(EI, outW);
    k_gemm   <<<dim3(2, 313), 256>>>(U, Ie, GW, out);
    k_scatter<<<1024, 256>>>(EI, out);
    k_final  <<<(NN * HID / 4 + 255) / 256, 256>>>(out, GB);
}

// round 14
// speedup vs baseline: 1.0840x; 1.0840x over previous
#include <cuda_runtime.h>
#include <cstdint>

// Problem constants (shapes fixed by the dataset)
#define NU   10000
#define NI   30000
#define NN   40000      // NU + NI
#define HID  256
#define NE   500000
#define AH   32
#define THR  0.8f

// ---------------- device scratch (no allocation allowed) ----------------
__device__ float g_A[NU * AH];             // U @ W1_top + b1
__device__ float g_B[NI * AH];             // I @ W1_bot
__device__ float g_w[NE];                  // raw sigmoid edge weights
__device__ float g_deg[NN];                // degree (self-loop = 1)
__device__ float g_Y[(size_t)NN * HID];    // dinv[row] * (x @ gcn_W)
__device__ int   g_kept[NE];               // compacted kept-edge ids
__device__ int   g_nkept;
__device__ int   g_any;
__device__ unsigned long long g_amax;      // packed (w_bits << 32) | ~idx

// ---------------- K1: A = U@W1u + b1 ; B = I@W1i  (+ fused state reset) -----
__global__ __launch_bounds__(256) void k_ab(const float* __restrict__ U,
                                            const float* __restrict__ Iemb,
                                            const float* __restrict__ W1,
                                            const float* __restrict__ b1) {
    __shared__ __align__(16) float Wt[AH * 260];
    int tid  = threadIdx.x;
    int gt   = blockIdx.x * 256 + tid;
    if (gt < NN) g_deg[gt] = 1.0f;
    if (gt == 0) { g_any = 0; g_nkept = 0; g_amax = 0ull; }

    int row0 = blockIdx.x * 8;
    int half = (row0 >= NU) ? 1 : 0;    // 10000 % 8 == 0, no block crosses boundary
    const float* Wbase = W1 + half * HID * AH;
    for (int idx = tid; idx < HID * AH; idx += 256)
        Wt[(idx & 31) * 260 + (idx >> 5)] = Wbase[idx];
    __syncthreads();

    int r = tid >> 5;
    int j = tid & 31;
    int row = row0 + r;
    const float* xrow = half ? (Iemb + (size_t)(row - NU) * HID)
                             : (U + (size_t)row * HID);
    float acc = half ? 0.f : b1[j];
    const float* wrow = &Wt[j * 260];
#pragma unroll 8
    for (int k = 0; k < HID; k += 4) {
        float4 x4 = *(const float4*)(xrow + k);   // broadcast across warp
        float4 w4 = *(const float4*)(wrow + k);
        acc += x4.x * w4.x + x4.y * w4.y + x4.z * w4.z + x4.w * w4.w;
    }
    if (half) g_B[(row - NU) * AH + j] = acc;
    else      g_A[row * AH + j] = acc;
}

// ---------------- K2: per-edge MLP + sigmoid (warp per edge) ----------------
__global__ __launch_bounds__(256) void k_edge(const int* __restrict__ ei,
                                              const float* __restrict__ W2,
                                              const float* __restrict__ b2) {
    int gt   = blockIdx.x * blockDim.x + threadIdx.x;
    int e    = gt >> 5;
    int lane = gt & 31;
    if (e >= NE) return;
    int s = __ldg(&ei[e]);
    int d = __ldg(&ei[NE + e]);
    float h = g_A[s * AH + lane] + g_B[d * AH + lane];
    h = (h > 0.f) ? h : 0.2f * h;                  // leaky_relu(0.2)
    float p = h * W2[lane];
#pragma unroll
    for (int o = 16; o; o >>= 1) p += __shfl_xor_sync(0xffffffffu, p, o);
    if (lane == 0) {
        float wgt = 1.f / (1.f + expf(-(p + b2[0])));
        g_w[e] = wgt;
        if (wgt > THR) g_any = 1;   // benign race: all writers store 1
    }
}

// ---------------- K3: argmax fallback (only does work if no edge passed) ----
__global__ void k_argmax() {
    if (g_any) return;
    __shared__ unsigned long long smax;
    if (threadIdx.x == 0) smax = 0ull;
    __syncthreads();
    unsigned long long best = 0ull;
    for (int e = blockIdx.x * blockDim.x + threadIdx.x; e < NE;
         e += gridDim.x * blockDim.x) {
        unsigned long long pk =
            ((unsigned long long)__float_as_uint(g_w[e]) << 32) |
            (unsigned int)(~(unsigned int)e);
        if (pk > best) best = pk;
    }
    atomicMax(&smax, best);
    __syncthreads();
    if (threadIdx.x == 0) atomicMax(&g_amax, smax);
}

// ------- K4: mask + denoised weights out + degree atomics + compaction ------
__global__ __launch_bounds__(256) void k_mask(const int* __restrict__ ei,
                                              float* __restrict__ out_w) {
    __shared__ int s_base;
    __shared__ int warp_off[8];
    int e    = blockIdx.x * blockDim.x + threadIdx.x;
    int lane = threadIdx.x & 31;
    int warp = threadIdx.x >> 5;
    bool keep = false;
    if (e < NE) {
        float w = g_w[e];
        keep = (w > THR);
        if (!g_any) {
            int am = (int)(~(unsigned int)(g_amax & 0xffffffffull));
            keep = (e == am);
        }
        out_w[e] = keep ? w : 0.f;
        if (keep) atomicAdd(&g_deg[ei[NE + e]], 1.0f);
    }
    unsigned bal = __ballot_sync(0xffffffffu, keep);
    if (lane == 0) warp_off[warp] = __popc(bal);
    __syncthreads();
    if (threadIdx.x == 0) {
        int tot = 0;
#pragma unroll
        for (int i = 0; i < 8; i++) { int c = warp_off[i]; warp_off[i] = tot; tot += c; }
        s_base = atomicAdd(&g_nkept, tot);
    }
    __syncthreads();
    if (keep) {
        int idx = s_base + warp_off[warp] + __popc(bal & ((1u << lane) - 1));
        g_kept[idx] = e;
    }
}

// ---------------- K5: y = dinv[row] * (x @ gcn_W); acc(=d_out) = y ----------
// 128x128 tile, BK=16, 256 threads, 8x8 register tile per thread.
// Inner product uses packed fma.rn.f32x2 (2 FP32 FMA / instr; FFMA2 pipe rt=2
// -> 128 FMA-lanes/cyc/SM, 2x the scalar-FFMA floor). B pairs are contiguous
// columns so Bs loads directly as packed b64; thread's columns {4tx..4tx+3}
// and {64+4tx..} give conflict-free 16B-stride LDS.128 (old tx*8 map was
// 4-way conflicted). Bit-identical FP32 arithmetic.
__global__ __launch_bounds__(256, 2) void k_gemm(const float* __restrict__ U,
                                                 const float* __restrict__ Iemb,
                                                 const float* __restrict__ W,
                                                 float* __restrict__ outAcc) {
    __shared__ __align__(16) float As[128 * 17];   // [r][k], padded
    __shared__ __align__(16) float Bs[16 * 128];   // [k][c]
    int tid = threadIdx.x;
    int tx = tid & 15, ty = tid >> 4;
    int bn = blockIdx.x * 128;
    int bm = blockIdx.y * 128;

    unsigned long long acc2[8][4];   // 8 rows x 4 packed col-pairs (8 cols)
#pragma unroll
    for (int i = 0; i < 8; i++)
#pragma unroll
        for (int j = 0; j < 4; j++) acc2[i][j] = 0ull;

    for (int k0 = 0; k0 < 256; k0 += 16) {
#pragma unroll
        for (int l = 0; l < 2; l++) {           // A tile: 128x16
            int f = tid + l * 256;              // float4 index
            int r = f >> 2, c4 = f & 3;
            int row = bm + r;
            float4 v = make_float4(0.f, 0.f, 0.f, 0.f);
            if (row < NN) {
                const float* xr = (row < NU) ? (U + (size_t)row * HID)
                                             : (Iemb + (size_t)(row - NU) * HID);
                v = *(const float4*)(xr + k0 + c4 * 4);
            }
            As[r * 17 + c4 * 4 + 0] = v.x;
            As[r * 17 + c4 * 4 + 1] = v.y;
            As[r * 17 + c4 * 4 + 2] = v.z;
            As[r * 17 + c4 * 4 + 3] = v.w;
        }
#pragma unroll
        for (int l = 0; l < 2; l++) {           // B tile: 16x128
            int f = tid + l * 256;
            int k = f >> 5, c4 = f & 31;
            float4 v = *(const float4*)(W + (size_t)(k0 + k) * 256 + bn + c4 * 4);
            *(float4*)&Bs[k * 128 + c4 * 4] = v;
        }
        __syncthreads();
#pragma unroll
        for (int kk = 0; kk < 16; kk++) {
            // 4 packed col-pairs: cols {4tx..4tx+3} and {64+4tx..64+4tx+3}
            ulonglong2 b01 = *(const ulonglong2*)&Bs[kk * 128 + tx * 4];
            ulonglong2 b23 = *(const ulonglong2*)&Bs[kk * 128 + 64 + tx * 4];
            unsigned long long bp0 = b01.x, bp1 = b01.y;
            unsigned long long bp2 = b23.x, bp3 = b23.y;
#pragma unroll
            for (int i = 0; i < 8; i++) {
                float av = As[(ty * 8 + i) * 17 + kk];
                unsigned long long ap;
                asm("mov.b64 %0, {%1, %1};" : "=l"(ap) : "f"(av));
                asm("fma.rn.f32x2 %0, %1, %2, %0;" : "+l"(acc2[i][0]) : "l"(ap), "l"(bp0));
                asm("fma.rn.f32x2 %0, %1, %2, %0;" : "+l"(acc2[i][1]) : "l"(ap), "l"(bp1));
                asm("fma.rn.f32x2 %0, %1, %2, %0;" : "+l"(acc2[i][2]) : "l"(ap), "l"(bp2));
                asm("fma.rn.f32x2 %0, %1, %2, %0;" : "+l"(acc2[i][3]) : "l"(ap), "l"(bp3));
            }
        }
        __syncthreads();
    }

#pragma unroll
    for (int i = 0; i < 8; i++) {
        int row = bm + ty * 8 + i;
        if (row < NN) {
            float dv = rsqrtf(g_deg[row]);
#pragma unroll
            for (int g = 0; g < 2; g++) {       // col group: 4tx and 64+4tx
                float4 v;
                asm("mov.b64 {%0, %1}, %2;" : "=f"(v.x), "=f"(v.y) : "l"(acc2[i][g * 2 + 0]));
                asm("mov.b64 {%0, %1}, %2;" : "=f"(v.z), "=f"(v.w) : "l"(acc2[i][g * 2 + 1]));
                v.x *= dv; v.y *= dv; v.z *= dv; v.w *= dv;
                size_t off = (size_t)row * HID + bn + g * 64 + tx * 4;
                *(float4*)(g_Y + off)    = v;   // read source for messages
                *(float4*)(outAcc + off) = v;   // accumulator (self term)
            }
        }
    }
}

// ---------------- K6: scatter kept-edge messages: acc[dst] += y[src] --------
__global__ __launch_bounds__(256) void k_scatter(const int* __restrict__ ei,
                                                 float* __restrict__ outAcc) {
    int nk    = g_nkept;
    int lane  = threadIdx.x & 31;
    int wid   = (blockIdx.x * blockDim.x + threadIdx.x) >> 5;
    int nwarp = (gridDim.x * blockDim.x) >> 5;
    for (int i = wid; i < nk; i += nwarp) {
        int e = g_kept[i];
        int s = ei[e];
        int d = ei[NE + e];
        const float4* ys = (const float4*)(g_Y + (size_t)s * HID);
        float4* od = (float4*)(outAcc + (size_t)d * HID);
#pragma unroll
        for (int jj = 0; jj < 2; jj++) {
            float4 v = ys[lane + 32 * jj];
            asm volatile("red.global.add.v4.f32 [%0], {%1, %2, %3, %4};"
                         :: "l"(od + lane + 32 * jj),
                            "f"(v.x), "f"(v.y), "f"(v.z), "f"(v.w)
                         : "memory");
        }
    }
}

// ---------------- K7: out = dinv[row]*acc + gcn_b ----------------
__global__ void k_final(float* __restrict__ out, const float* __restrict__ gb) {
    int i = blockIdx.x * blockDim.x + threadIdx.x;
    if (i >= NN * HID / 4) return;
    float4 v = ((float4*)out)[i];
    int row = i >> 6;    // 64 float4 per row
    int c4  = i & 63;
    float dv = rsqrtf(g_deg[row]);
    float4 b = ((const float4*)gb)[c4];
    v.x = v.x * dv + b.x;
    v.y = v.y * dv + b.y;
    v.z = v.z * dv + b.z;
    v.w = v.w * dv + b.w;
    ((float4*)out)[i] = v;
}

// ---------------- launch ----------------
extern "C" void kernel_launch(void* const* d_in, const int* in_sizes, int n_in,
                              void* d_out, int out_size) {
    const float* U  = (const float*)d_in[0];   // [10000,256]
    const float* Ie = (const float*)d_in[1];   // [30000,256]
    const int*   EI = (const int*)  d_in[2];   // [2,500000]
    const float* W1 = (const float*)d_in[3];   // [512,32]
    const float* B1 = (const float*)d_in[4];   // [32]
    const float* W2 = (const float*)d_in[5];   // [32,1]
    const float* B2 = (const float*)d_in[6];   // [1]
    const float* GW = (const float*)d_in[7];   // [256,256]
    const float* GB = (const float*)d_in[8];   // [256]
    float* out  = (float*)d_out;               // [40000,256] then [500000]
    float* outW = out + (size_t)NN * HID;

    k_ab     <<<NN / 8, 256>>>(U, Ie, W1, B1);   // includes state reset
    k_edge   <<<(NE * 32) / 256, 256>>>(EI, W2, B2);
    k_argmax <<<256, 256>>>();
    k_mask   <<<(NE + 255) / 256, 256>>>(EI, outW);
    k_gemm   <<<dim3(2, 313), 256>>>(U, Ie, GW, out);
    k_scatter<<<1024, 256>>>(EI, out);
    k_final  <<<(NN * HID / 4 + 255) / 256, 256>>>(out, GB);
}